// round 13
// baseline (speedup 1.0000x reference)
#include <cuda_runtime.h>
#include <cuda_fp16.h>
#include <math.h>
#include <stdint.h>

#define B 4
#define S 2048
#define H 768
#define NH 12
#define DH 64
#define WH 128
#define TOK (B*S)
#define EPS 1e-12f

__device__ float g_Q[(size_t)TOK*H];
__device__ float g_K[(size_t)TOK*H];   // dh pair-interleaved within 8-groups
__device__ float g_V[(size_t)TOK*H];
__device__ float g_ctx[(size_t)TOK*H];
__device__ float g_proj[(size_t)TOK*H];
__device__ float g_g1[(size_t)TOK*WH];
__device__ float g_gates[(size_t)TOK*NH];
__device__ float g_rowinv[(size_t)B*NH*S];
__device__ float g_msk[(size_t)B*S];
__device__ __half g_eh[(size_t)B*NH*S*S];   // unnormalized e, fp16

__device__ __forceinline__ void cpa16(void* dst, const void* src){
    uint32_t d = (uint32_t)__cvta_generic_to_shared(dst);
    asm volatile("cp.async.ca.shared.global [%0], [%1], 16;" :: "r"(d), "l"(src));
}
#define CPA_COMMIT() asm volatile("cp.async.commit_group;" ::: "memory")
#define CPA_WAIT0()  asm volatile("cp.async.wait_group 0;" ::: "memory")
#define CPA_WAIT1()  asm volatile("cp.async.wait_group 1;" ::: "memory")

__device__ __forceinline__ void mma8(float* c, const uint32_t* a, const uint32_t* b){
    asm volatile("mma.sync.aligned.m16n8k8.row.col.f32.tf32.tf32.f32 "
        "{%0,%1,%2,%3}, {%4,%5,%6,%7}, {%8,%9}, {%0,%1,%2,%3};"
        : "+f"(c[0]), "+f"(c[1]), "+f"(c[2]), "+f"(c[3])
        : "r"(a[0]), "r"(a[1]), "r"(a[2]), "r"(a[3]), "r"(b[0]), "r"(b[1]));
}
#define F2U __float_as_uint

#define GBM 128
#define GBN 128
#define GBK 16
#define ASZ (GBM*20)     // 2560 words per A stage
#define BSZ (GBK*136)    // 2176 words per B stage
#define GSMEM ((3*ASZ + 3*BSZ) * 4)

// ============ tf32 GEMM body, 3-stage cp.async pipeline ============
__device__ __forceinline__ void gemm_body(const float* __restrict__ A,
                                          const float* __restrict__ Wm,
                                          const float* __restrict__ bias,
                                          float* __restrict__ C,
                                          int m0, int n0, int ldc, int K, int kperm)
{
    extern __shared__ float gsm[];
    float* Asb = gsm;              // 3 x [128][20]
    float* Bsb = gsm + 3 * ASZ;    // 3 x [16][136]
    const int t = threadIdx.x, lane = t & 31, w = t >> 5;
    const int wr = w >> 1, wc = w & 1;
    const int qr = lane >> 2, qc = lane & 3;
    const int NIT = K / GBK;

    float acc[2][8][4];
#pragma unroll
    for (int mt = 0; mt < 2; mt++)
#pragma unroll
        for (int nt = 0; nt < 8; nt++)
#pragma unroll
            for (int i = 0; i < 4; i++) acc[mt][nt][i] = 0.f;

    auto issue = [&](int k0, int buf){
        float* As = Asb + buf * ASZ;
        float* Bs = Bsb + buf * BSZ;
#pragma unroll
        for (int i = 0; i < 2; i++) {
            int idx = t * 2 + i;
            int row = idx >> 2, c4 = (idx & 3) * 4;
            cpa16(&As[row * 20 + c4], &A[(size_t)(m0 + row) * K + k0 + c4]);
            int kk = idx >> 5, c42 = (idx & 31) * 4;
            cpa16(&Bs[kk * 136 + c42], &Wm[(size_t)(k0 + kk) * ldc + n0 + c42]);
        }
    };

    issue(0, 0); CPA_COMMIT();
    if (NIT > 1) { issue(GBK, 1); CPA_COMMIT(); }

    for (int i = 0; i < NIT; i++) {
        if (i + 1 < NIT) CPA_WAIT1(); else CPA_WAIT0();
        __syncthreads();                                 // tile i visible; buf (i+2)%3 free
        if (i + 2 < NIT) { issue((i + 2) * GBK, (i + 2) % 3); CPA_COMMIT(); }
        const float* As = Asb + (i % 3) * ASZ;
        const float* Bs = Bsb + (i % 3) * BSZ;
#pragma unroll
        for (int ks = 0; ks < 2; ks++) {
            const int kb = ks * 8;
            uint32_t aa[2][4];
#pragma unroll
            for (int mt = 0; mt < 2; mt++) {
                int mb = 32 * wr + 16 * mt;
                aa[mt][0] = F2U(As[(mb + qr) * 20 + kb + qc]);
                aa[mt][1] = F2U(As[(mb + qr + 8) * 20 + kb + qc]);
                aa[mt][2] = F2U(As[(mb + qr) * 20 + kb + qc + 4]);
                aa[mt][3] = F2U(As[(mb + qr + 8) * 20 + kb + qc + 4]);
            }
#pragma unroll
            for (int nt = 0; nt < 8; nt++) {
                int nb = 64 * wc + 8 * nt;
                uint32_t bb[2];
                bb[0] = F2U(Bs[(kb + qc) * 136 + nb + qr]);
                bb[1] = F2U(Bs[(kb + qc + 4) * 136 + nb + qr]);
                mma8(acc[0][nt], aa[0], bb);
                mma8(acc[1][nt], aa[1], bb);
            }
        }
    }

#pragma unroll
    for (int mt = 0; mt < 2; mt++)
#pragma unroll
        for (int nt = 0; nt < 8; nt++) {
            int row = m0 + 32 * wr + 16 * mt + qr;
            int col = n0 + 64 * wc + 8 * nt + 2 * qc;
            float b0 = bias[col], b1 = bias[col + 1];
            float v00 = acc[mt][nt][0] + b0, v01 = acc[mt][nt][1] + b1;
            float v10 = acc[mt][nt][2] + b0, v11 = acc[mt][nt][3] + b1;
            if (!kperm) {
                *(float2*)&C[(size_t)row * ldc + col]       = make_float2(v00, v01);
                *(float2*)&C[(size_t)(row + 8) * ldc + col] = make_float2(v10, v11);
            } else {
                int g = col & ~7, r = col & 7;
                int p0 = g + ((r < 4) ? 2 * r : 2 * (r - 4) + 1);
                int p1 = g + ((r + 1 < 4) ? 2 * (r + 1) : 2 * (r - 3) + 1);
                C[(size_t)row * ldc + p0] = v00;
                C[(size_t)row * ldc + p1] = v01;
                C[(size_t)(row + 8) * ldc + p0] = v10;
                C[(size_t)(row + 8) * ldc + p1] = v11;
            }
        }
}

__global__ __launch_bounds__(256) void gemm_qkvg(const float* __restrict__ X,
                                                 const float* __restrict__ Wq, const float* __restrict__ bq,
                                                 const float* __restrict__ Wk, const float* __restrict__ bk,
                                                 const float* __restrict__ Wv, const float* __restrict__ bv,
                                                 const float* __restrict__ Wg1, const float* __restrict__ bg1,
                                                 float* __restrict__ Q, float* __restrict__ K,
                                                 float* __restrict__ V, float* __restrict__ G1)
{
    const int bx = blockIdx.x;
    const float *Wm, *bias; float* C; int n0, ldc, kperm = 0;
    if (bx < 6)       { Wm = Wq;  bias = bq;  C = Q;  n0 = bx * 128;        ldc = H;  }
    else if (bx < 12) { Wm = Wk;  bias = bk;  C = K;  n0 = (bx - 6) * 128;  ldc = H;  kperm = 1; }
    else if (bx < 18) { Wm = Wv;  bias = bv;  C = V;  n0 = (bx - 12) * 128; ldc = H;  }
    else              { Wm = Wg1; bias = bg1; C = G1; n0 = 0;               ldc = WH; }
    gemm_body(X, Wm, bias, C, blockIdx.y * GBM, n0, ldc, H, kperm);
}

__global__ __launch_bounds__(256) void gemm_tf32(const float* __restrict__ A,
                                                 const float* __restrict__ Wm,
                                                 const float* __restrict__ bias,
                                                 float* __restrict__ C,
                                                 int M, int N, int K)
{
    gemm_body(A, Wm, bias, C, blockIdx.y * GBM, blockIdx.x * GBN, N, K, 0);
}

// ============ gate stage 2 ============
__global__ __launch_bounds__(256) void gate2_kernel(const float* __restrict__ g1,
                                                    const float* __restrict__ glnw,
                                                    const float* __restrict__ glnb,
                                                    const float* __restrict__ Wg2,
                                                    const float* __restrict__ bg2,
                                                    float* __restrict__ gates)
{
    __shared__ float W2s[WH * NH];
    __shared__ float ys[8][WH + 4];
    const int t = threadIdx.x, w = t >> 5, ln = t & 31;
    const int tok = blockIdx.x * 8 + w;

    for (int i = t; i < WH * NH; i += 256) W2s[i] = Wg2[i];
    __syncthreads();

    float4 x = *(const float4*)&g1[(size_t)tok * WH + ln * 4];
    float s  = x.x + x.y + x.z + x.w;
    float sq = x.x*x.x + x.y*x.y + x.z*x.z + x.w*x.w;
#pragma unroll
    for (int o = 16; o; o >>= 1) {
        s  += __shfl_xor_sync(0xffffffffu, s, o);
        sq += __shfl_xor_sync(0xffffffffu, sq, o);
    }
    float mu = s * (1.f / WH);
    float iv = rsqrtf(sq * (1.f / WH) - mu * mu + EPS);
    float4 wv = *(const float4*)&glnw[ln * 4];
    float4 bv = *(const float4*)&glnb[ln * 4];
    float4 y;
    y.x = fmaxf((x.x - mu) * iv * wv.x + bv.x, 0.f);
    y.y = fmaxf((x.y - mu) * iv * wv.y + bv.y, 0.f);
    y.z = fmaxf((x.z - mu) * iv * wv.z + bv.z, 0.f);
    y.w = fmaxf((x.w - mu) * iv * wv.w + bv.w, 0.f);
    *(float4*)&ys[w][ln * 4] = y;
    __syncwarp();
    if (ln < NH) {
        float acc = bg2[ln];
#pragma unroll 4
        for (int k = 0; k < WH; k++) acc += ys[w][k] * W2s[k * NH + ln];
        gates[(size_t)tok * NH + ln] = 1.f / (1.f + __expf(-acc));
    }
}

// ============ mask precompute ============
__global__ __launch_bounds__(512) void mask_prep(const float* __restrict__ am,
                                                 float* __restrict__ msk)
{
    int i = blockIdx.x * 512 + threadIdx.x;
    msk[i] = (1.f - am[i]) * -10000.f;
}

// ============ attention: SW-pipelined, e written as fp16 ============
#define KSTR 72
#define VSTR 72
#define PSZ  5120

__global__ __launch_bounds__(512) void attn_onepass(float* __restrict__ rowinv)
{
    extern __shared__ float sm[];
    float* Qs    = sm;                    // 64x68
    float* KsA   = Qs + 4352;             // 3 x 64x72
    float* VsA   = KsA + 3 * 64 * KSTR;   // 3 x 64x72
    float* PsA   = VsA + 3 * 64 * VSTR;   // 2 x PSZ packed
    float* gt    = PsA + 2 * PSZ;
    float* redS  = gt + 64;
    float* rowIs = redS + 256;

    const int t = threadIdx.x, lane = t & 31, w = t >> 5;
    const int wr = w >> 2, wk = w & 3;
    const int qr = lane >> 2, qc = lane & 3;
    const int q0 = blockIdx.x * 64;
    const int h  = blockIdx.y;
    const int b  = blockIdx.z;
    const int NT = S / 64;

    const float* Qg = g_Q + ((size_t)(b * S + q0)) * H + h * DH;
    const float* Kg = g_K + ((size_t)b * S) * H + h * DH;
    const float* Vg = g_V + ((size_t)b * S) * H + h * DH;
    const float* mskb = g_msk + (size_t)b * S;
    __half* eout = g_eh + (((size_t)b * NH + h) * S + q0) * S;

    auto issueKV = [&](int kt){
        int buf = kt % 3;
        float* Kd = KsA + buf * 64 * KSTR;
        float* Vd = VsA + buf * 64 * VSTR;
#pragma unroll
        for (int i = 0; i < 2; i++) {
            int idx = t + i * 512;
            int r = idx >> 4, c4 = (idx & 15) * 4;
            cpa16(&Kd[r * KSTR + c4], &Kg[(size_t)(kt * 64 + r) * H + c4]);
            cpa16(&Vd[r * VSTR + c4], &Vg[(size_t)(kt * 64 + r) * H + c4]);
        }
    };

    {
#pragma unroll
        for (int i = 0; i < 2; i++) {
            int idx = t + i * 512;
            int r = idx >> 4, c4 = (idx & 15) * 4;
            cpa16(&Qs[r * 68 + c4], &Qg[(size_t)r * H + c4]);
        }
        issueKV(0);
        CPA_COMMIT();
        if (t < 64) gt[t] = g_gates[(size_t)(b * S + q0 + t) * NH + h] * 0.125f;
        CPA_WAIT0();
    }
    __syncthreads();

    const float g0 = gt[wr * 16 + qr], g1v = gt[wr * 16 + qr + 8];
    const int r0 = (wr * 16 + qr) * 68, r1 = (wr * 16 + qr + 8) * 68;

    uint32_t qa[8][4];
#pragma unroll
    for (int ks = 0; ks < 8; ks++) {
        int kc = ks * 8 + qc;
        qa[ks][0] = F2U(Qs[r0 + kc]);
        qa[ks][1] = F2U(Qs[r1 + kc]);
        qa[ks][2] = F2U(Qs[r0 + kc + 4]);
        qa[ks][3] = F2U(Qs[r1 + kc + 4]);
    }

    float s0 = 0.f, s1 = 0.f;
    float cacc[2][4] = {{0.f,0.f,0.f,0.f},{0.f,0.f,0.f,0.f}};

    const int qcA   = (qc < 2) ? 2 * qc : 2 * qc - 4;
    const int slotA = (qc < 2) ? 0 : 2;

    auto doPV = [&](int j){
        const float* Pb = PsA + (j & 1) * PSZ;
        const float* Vb = VsA + (j % 3) * 64 * VSTR;
#pragma unroll
        for (int ks = 0; ks < 8; ks++) {
            float4 av = *(const float4*)&Pb[((wr * 8 + ks) * 4 + qc) * 40 + qr * 4];
#pragma unroll
            for (int j2 = 0; j2 < 2; j2++) {
                int nb = (wk * 2 + j2) * 8;
                uint32_t bb[2];
                bb[0] = F2U(Vb[(ks * 8 + qc) * VSTR + nb + qr]);
                bb[1] = F2U(Vb[(ks * 8 + qc + 4) * VSTR + nb + qr]);
                mma8(cacc[j2], (const uint32_t*)&av, bb);
            }
        }
    };

    for (int kt = 0; kt < NT; kt++) {
        if (kt > 0) { CPA_WAIT0(); __syncthreads(); }
        if (kt + 1 < NT) { issueKV(kt + 1); CPA_COMMIT(); }

        {
            const float* Kb = KsA + (kt % 3) * 64 * KSTR;
            float* Pw = PsA + (kt & 1) * PSZ;
            float c0[4] = {0.f,0.f,0.f,0.f}, c1[4] = {0.f,0.f,0.f,0.f};
#pragma unroll
            for (int ks = 0; ks < 8; ks++) {
                float2 bv0 = *(const float2*)&Kb[(wk * 16 + qr) * KSTR + ks * 8 + 2 * qc];
                mma8(c0, qa[ks], (const uint32_t*)&bv0);
                float2 bv1 = *(const float2*)&Kb[(wk * 16 + 8 + qr) * KSTR + ks * 8 + 2 * qc];
                mma8(c1, qa[ks], (const uint32_t*)&bv1);
            }
#pragma unroll
            for (int nt = 0; nt < 2; nt++) {
                float* c = nt ? c1 : c0;
                int lc = wk * 16 + nt * 8 + 2 * qc;
                int col = kt * 64 + lc;
                float2 mk = __ldg((const float2*)&mskb[col]);
                float e00 = __expf(c[0] * g0  + mk.x);
                float e01 = __expf(c[1] * g0  + mk.y);
                float e10 = __expf(c[2] * g1v + mk.x);
                float e11 = __expf(c[3] * g1v + mk.y);
                s0 += e00 + e01;
                s1 += e10 + e11;
                int ksl = wk * 2 + nt;
                float* basep = Pw + ((wr * 8 + ksl) * 4 + qcA) * 40 + qr * 4 + slotA;
                *(float2*)basep        = make_float2(e00, e10);
                *(float2*)(basep + 40) = make_float2(e01, e11);
                *(__half2*)&eout[(size_t)(wr * 16 + qr) * S + col]     = __floats2half2_rn(e00, e01);
                *(__half2*)&eout[(size_t)(wr * 16 + qr + 8) * S + col] = __floats2half2_rn(e10, e11);
            }
        }

        if (kt > 0) doPV(kt - 1);
    }
    __syncthreads();
    doPV(NT - 1);

#pragma unroll
    for (int off = 1; off <= 2; off <<= 1) {
        s0 += __shfl_xor_sync(0xffffffffu, s0, off);
        s1 += __shfl_xor_sync(0xffffffffu, s1, off);
    }
    if (qc == 0) {
        redS[wk * 64 + wr * 16 + qr]     = s0;
        redS[wk * 64 + wr * 16 + qr + 8] = s1;
    }
    __syncthreads();
    if (t < 64) {
        float s = redS[t] + redS[64 + t] + redS[128 + t] + redS[192 + t];
        float inv = 1.f / s;
        rowIs[t] = inv;
        rowinv[((size_t)b * NH + h) * S + q0 + t] = inv;
    }
    __syncthreads();
    const float I0 = rowIs[wr * 16 + qr], I1 = rowIs[wr * 16 + qr + 8];

#pragma unroll
    for (int j = 0; j < 2; j++) {
        int nb = (wk * 2 + j) * 8;
        size_t row = (size_t)b * S + q0 + wr * 16 + qr;
        int col = h * DH + nb + 2 * qc;
        *(float2*)&g_ctx[row * H + col]       = make_float2(cacc[j][0] * I0, cacc[j][1] * I0);
        *(float2*)&g_ctx[(row + 8) * H + col] = make_float2(cacc[j][2] * I1, cacc[j][3] * I1);
    }
}

// ============ probs normalization: fp16 e -> fp32 normalized probs ============
__global__ __launch_bounds__(512) void scale_probs(float* __restrict__ probs,
                                                   const float* __restrict__ rowinv)
{
    const int t = threadIdx.x;
    const int rloc = t >> 7;            // 0..3
    const int cid  = t & 127;           // 0..127, 16 cols each
    const size_t row = (size_t)blockIdx.x * 4 + rloc;
    const float inv = __ldg(&rowinv[row]);
    const __half* er = g_eh + row * (size_t)S + cid * 16;
    uint4 ha = *(const uint4*)er;            // 8 halves
    uint4 hb = *(const uint4*)(er + 8);      // 8 halves
    float* po = probs + row * (size_t)S + cid * 16;
    const uint32_t* hw[2] = { &ha.x, &hb.x };
#pragma unroll
    for (int half8 = 0; half8 < 2; half8++) {
#pragma unroll
        for (int i = 0; i < 4; i++) {
            float2 f = __half22float2(*(const __half2*)&hw[half8][i]);
            float2 o = make_float2(f.x * inv, f.y * inv);
            *(float2*)&po[half8 * 8 + i * 2] = o;
        }
    }
}

// ============ residual + LayerNorm(768) ============
__global__ __launch_bounds__(256) void ln_kernel(const float* __restrict__ P,
                                                 const float* __restrict__ Xres,
                                                 const float* __restrict__ wgt,
                                                 const float* __restrict__ bb,
                                                 float* __restrict__ out)
{
    const int tok = blockIdx.x;
    const int t = threadIdx.x;
    __shared__ float rs[8], rq[8];
    __shared__ float smu, siv;

    float v[3];
    float s = 0.f, sq = 0.f;
#pragma unroll
    for (int i = 0; i < 3; i++) {
        int c = t + i * 256;
        float x = P[(size_t)tok * H + c] + Xres[(size_t)tok * H + c];
        v[i] = x; s += x; sq += x * x;
    }
    for (int o = 16; o; o >>= 1) {
        s  += __shfl_xor_sync(0xffffffffu, s, o);
        sq += __shfl_xor_sync(0xffffffffu, sq, o);
    }
    int wi = t >> 5, ln = t & 31;
    if (ln == 0) { rs[wi] = s; rq[wi] = sq; }
    __syncthreads();
    if (t == 0) {
        float ts = 0.f, tq = 0.f;
#pragma unroll
        for (int i = 0; i < 8; i++) { ts += rs[i]; tq += rq[i]; }
        float mu = ts * (1.f / H);
        smu = mu;
        siv = rsqrtf(tq * (1.f / H) - mu * mu + EPS);
    }
    __syncthreads();
    float mu = smu, iv = siv;
#pragma unroll
    for (int i = 0; i < 3; i++) {
        int c = t + i * 256;
        out[(size_t)tok * H + c] = (v[i] - mu) * iv * wgt[c] + bb[c];
    }
}

// ============ launch ============
extern "C" void kernel_launch(void* const* d_in, const int* in_sizes, int n_in,
                              void* d_out, int out_size)
{
    const float* X    = (const float*)d_in[0];
    const float* am   = (const float*)d_in[1];
    const float* Wq   = (const float*)d_in[2];
    const float* bq   = (const float*)d_in[3];
    const float* Wk   = (const float*)d_in[4];
    const float* bk   = (const float*)d_in[5];
    const float* Wv   = (const float*)d_in[6];
    const float* bv   = (const float*)d_in[7];
    const float* Wg1  = (const float*)d_in[8];
    const float* bg1  = (const float*)d_in[9];
    const float* glnw = (const float*)d_in[10];
    const float* glnb = (const float*)d_in[11];
    const float* Wg2  = (const float*)d_in[12];
    const float* bg2  = (const float*)d_in[13];
    const float* Wo   = (const float*)d_in[14];
    const float* bo   = (const float*)d_in[15];
    const float* lnw  = (const float*)d_in[16];
    const float* lnb  = (const float*)d_in[17];

    float* out   = (float*)d_out;
    float* probs = out + (size_t)B * S * H;

    float *Qp, *Kp, *Vp, *Cp, *Pp, *G1p, *Gp, *Rp, *Mp;
    cudaGetSymbolAddress((void**)&Qp, g_Q);
    cudaGetSymbolAddress((void**)&Kp, g_K);
    cudaGetSymbolAddress((void**)&Vp, g_V);
    cudaGetSymbolAddress((void**)&Cp, g_ctx);
    cudaGetSymbolAddress((void**)&Pp, g_proj);
    cudaGetSymbolAddress((void**)&G1p, g_g1);
    cudaGetSymbolAddress((void**)&Gp, g_gates);
    cudaGetSymbolAddress((void**)&Rp, g_rowinv);
    cudaGetSymbolAddress((void**)&Mp, g_msk);

    cudaFuncSetAttribute(gemm_qkvg, cudaFuncAttributeMaxDynamicSharedMemorySize, GSMEM);
    cudaFuncSetAttribute(gemm_tf32, cudaFuncAttributeMaxDynamicSharedMemorySize, GSMEM);

    dim3 gfused(19, TOK / GBM);
    gemm_qkvg<<<gfused, 256, GSMEM>>>(X, Wq, bq, Wk, bk, Wv, bv, Wg1, bg1, Qp, Kp, Vp, G1p);

    gate2_kernel<<<TOK / 8, 256>>>(G1p, glnw, glnb, Wg2, bg2, Gp);

    mask_prep<<<B * S / 512, 512>>>(am, Mp);

    size_t att_smem = (size_t)(4352 + 3*64*KSTR + 3*64*VSTR + 2*PSZ + 64 + 256 + 64) * sizeof(float);
    cudaFuncSetAttribute(attn_onepass, cudaFuncAttributeMaxDynamicSharedMemorySize, (int)att_smem);
    dim3 gatt(S / 64, NH, B);
    attn_onepass<<<gatt, 512, att_smem>>>(Rp);

    scale_probs<<<B * NH * S / 4, 512>>>(probs, Rp);

    dim3 ggemm(H / GBN, TOK / GBM);
    gemm_tf32<<<ggemm, 256, GSMEM>>>(Cp, Wo, bo, Pp, TOK, H, H);

    ln_kernel<<<TOK, 256>>>(Pp, X, lnw, lnb, out);
}

// round 15
// speedup vs baseline: 1.1513x; 1.1513x over previous
#include <cuda_runtime.h>
#include <cuda_fp16.h>
#include <math.h>
#include <stdint.h>

#define B 4
#define S 2048
#define H 768
#define NH 12
#define DH 64
#define WH 128
#define TOK (B*S)
#define EPS 1e-12f

__device__ float g_Q[(size_t)TOK*H];
__device__ float g_K[(size_t)TOK*H];   // dh pair-interleaved within 8-groups
__device__ float g_V[(size_t)TOK*H];
__device__ float g_ctx[(size_t)TOK*H];
__device__ float g_proj[(size_t)TOK*H];
__device__ float g_g1[(size_t)TOK*WH];
__device__ float g_gates[(size_t)TOK*NH];
__device__ float g_rowinv[(size_t)B*NH*S];
__device__ float g_msk[(size_t)B*S];
__device__ __half g_eh[(size_t)B*NH*S*S];   // unnormalized e, fp16

__device__ __forceinline__ void cpa16(void* dst, const void* src){
    uint32_t d = (uint32_t)__cvta_generic_to_shared(dst);
    asm volatile("cp.async.ca.shared.global [%0], [%1], 16;" :: "r"(d), "l"(src));
}
#define CPA_COMMIT() asm volatile("cp.async.commit_group;" ::: "memory")
#define CPA_WAIT0()  asm volatile("cp.async.wait_group 0;" ::: "memory")
#define CPA_WAIT1()  asm volatile("cp.async.wait_group 1;" ::: "memory")

__device__ __forceinline__ void mma8(float* c, const uint32_t* a, const uint32_t* b){
    asm volatile("mma.sync.aligned.m16n8k8.row.col.f32.tf32.tf32.f32 "
        "{%0,%1,%2,%3}, {%4,%5,%6,%7}, {%8,%9}, {%0,%1,%2,%3};"
        : "+f"(c[0]), "+f"(c[1]), "+f"(c[2]), "+f"(c[3])
        : "r"(a[0]), "r"(a[1]), "r"(a[2]), "r"(a[3]), "r"(b[0]), "r"(b[1]));
}
#define F2U __float_as_uint

#define GBM 128
#define GBN 128
#define GBK 16

// ============ tf32 GEMM body, 2-stage double buffer (R12 known-good) ============
__device__ __forceinline__ void gemm_body(const float* __restrict__ A,
                                          const float* __restrict__ Wm,
                                          const float* __restrict__ bias,
                                          float* __restrict__ C,
                                          int m0, int n0, int ldc, int K, int kperm)
{
    __shared__ float As[2][GBM][20];
    __shared__ float Bs[2][GBK][136];
    const int t = threadIdx.x, lane = t & 31, w = t >> 5;
    const int wr = w >> 1, wc = w & 1;
    const int qr = lane >> 2, qc = lane & 3;
    const int NIT = K / GBK;

    float acc[2][8][4];
#pragma unroll
    for (int mt = 0; mt < 2; mt++)
#pragma unroll
        for (int nt = 0; nt < 8; nt++)
#pragma unroll
            for (int i = 0; i < 4; i++) acc[mt][nt][i] = 0.f;

    auto issue = [&](int k0, int buf){
#pragma unroll
        for (int i = 0; i < 2; i++) {
            int idx = t * 2 + i;
            int row = idx >> 2, c4 = (idx & 3) * 4;
            cpa16(&As[buf][row][c4], &A[(size_t)(m0 + row) * K + k0 + c4]);
            int kk = idx >> 5, c42 = (idx & 31) * 4;
            cpa16(&Bs[buf][kk][c42], &Wm[(size_t)(k0 + kk) * ldc + n0 + c42]);
        }
    };

    issue(0, 0); CPA_COMMIT();

    for (int i = 0; i < NIT; i++) {
        if (i + 1 < NIT) { issue((i + 1) * GBK, (i + 1) & 1); CPA_COMMIT(); CPA_WAIT1(); }
        else             { CPA_WAIT0(); }
        __syncthreads();
        const int buf = i & 1;
#pragma unroll
        for (int ks = 0; ks < 2; ks++) {
            const int kb = ks * 8;
            uint32_t aa[2][4];
#pragma unroll
            for (int mt = 0; mt < 2; mt++) {
                int mb = 32 * wr + 16 * mt;
                aa[mt][0] = F2U(As[buf][mb + qr][kb + qc]);
                aa[mt][1] = F2U(As[buf][mb + qr + 8][kb + qc]);
                aa[mt][2] = F2U(As[buf][mb + qr][kb + qc + 4]);
                aa[mt][3] = F2U(As[buf][mb + qr + 8][kb + qc + 4]);
            }
#pragma unroll
            for (int nt = 0; nt < 8; nt++) {
                int nb = 64 * wc + 8 * nt;
                uint32_t bb[2];
                bb[0] = F2U(Bs[buf][kb + qc][nb + qr]);
                bb[1] = F2U(Bs[buf][kb + qc + 4][nb + qr]);
                mma8(acc[0][nt], aa[0], bb);
                mma8(acc[1][nt], aa[1], bb);
            }
        }
        __syncthreads();
    }

#pragma unroll
    for (int mt = 0; mt < 2; mt++)
#pragma unroll
        for (int nt = 0; nt < 8; nt++) {
            int row = m0 + 32 * wr + 16 * mt + qr;
            int col = n0 + 64 * wc + 8 * nt + 2 * qc;
            float b0 = bias[col], b1 = bias[col + 1];
            float v00 = acc[mt][nt][0] + b0, v01 = acc[mt][nt][1] + b1;
            float v10 = acc[mt][nt][2] + b0, v11 = acc[mt][nt][3] + b1;
            if (!kperm) {
                *(float2*)&C[(size_t)row * ldc + col]       = make_float2(v00, v01);
                *(float2*)&C[(size_t)(row + 8) * ldc + col] = make_float2(v10, v11);
            } else {
                int g = col & ~7, r = col & 7;       // r = 2*qc (even)
                int p0 = g + ((r < 4) ? 2 * r : 2 * (r - 4) + 1);
                int p1 = g + ((r + 1 < 4) ? 2 * (r + 1) : 2 * (r - 3) + 1);
                C[(size_t)row * ldc + p0] = v00;
                C[(size_t)row * ldc + p1] = v01;
                C[(size_t)(row + 8) * ldc + p0] = v10;
                C[(size_t)(row + 8) * ldc + p1] = v11;
            }
        }
}

__global__ __launch_bounds__(256) void gemm_qkvg(const float* __restrict__ X,
                                                 const float* __restrict__ Wq, const float* __restrict__ bq,
                                                 const float* __restrict__ Wk, const float* __restrict__ bk,
                                                 const float* __restrict__ Wv, const float* __restrict__ bv,
                                                 const float* __restrict__ Wg1, const float* __restrict__ bg1,
                                                 float* __restrict__ Q, float* __restrict__ K,
                                                 float* __restrict__ V, float* __restrict__ G1)
{
    const int bx = blockIdx.x;
    const float *Wm, *bias; float* C; int n0, ldc, kperm = 0;
    if (bx < 6)       { Wm = Wq;  bias = bq;  C = Q;  n0 = bx * 128;        ldc = H;  }
    else if (bx < 12) { Wm = Wk;  bias = bk;  C = K;  n0 = (bx - 6) * 128;  ldc = H;  kperm = 1; }
    else if (bx < 18) { Wm = Wv;  bias = bv;  C = V;  n0 = (bx - 12) * 128; ldc = H;  }
    else              { Wm = Wg1; bias = bg1; C = G1; n0 = 0;               ldc = WH; }
    gemm_body(X, Wm, bias, C, blockIdx.y * GBM, n0, ldc, H, kperm);
}

__global__ __launch_bounds__(256) void gemm_tf32(const float* __restrict__ A,
                                                 const float* __restrict__ Wm,
                                                 const float* __restrict__ bias,
                                                 float* __restrict__ C,
                                                 int M, int N, int K)
{
    gemm_body(A, Wm, bias, C, blockIdx.y * GBM, blockIdx.x * GBN, N, K, 0);
}

// ============ gate stage 2 ============
__global__ __launch_bounds__(256) void gate2_kernel(const float* __restrict__ g1,
                                                    const float* __restrict__ glnw,
                                                    const float* __restrict__ glnb,
                                                    const float* __restrict__ Wg2,
                                                    const float* __restrict__ bg2,
                                                    float* __restrict__ gates)
{
    __shared__ float W2s[WH * NH];
    __shared__ float ys[8][WH + 4];
    const int t = threadIdx.x, w = t >> 5, ln = t & 31;
    const int tok = blockIdx.x * 8 + w;

    for (int i = t; i < WH * NH; i += 256) W2s[i] = Wg2[i];
    __syncthreads();

    float4 x = *(const float4*)&g1[(size_t)tok * WH + ln * 4];
    float s  = x.x + x.y + x.z + x.w;
    float sq = x.x*x.x + x.y*x.y + x.z*x.z + x.w*x.w;
#pragma unroll
    for (int o = 16; o; o >>= 1) {
        s  += __shfl_xor_sync(0xffffffffu, s, o);
        sq += __shfl_xor_sync(0xffffffffu, sq, o);
    }
    float mu = s * (1.f / WH);
    float iv = rsqrtf(sq * (1.f / WH) - mu * mu + EPS);
    float4 wv = *(const float4*)&glnw[ln * 4];
    float4 bv = *(const float4*)&glnb[ln * 4];
    float4 y;
    y.x = fmaxf((x.x - mu) * iv * wv.x + bv.x, 0.f);
    y.y = fmaxf((x.y - mu) * iv * wv.y + bv.y, 0.f);
    y.z = fmaxf((x.z - mu) * iv * wv.z + bv.z, 0.f);
    y.w = fmaxf((x.w - mu) * iv * wv.w + bv.w, 0.f);
    *(float4*)&ys[w][ln * 4] = y;
    __syncwarp();
    if (ln < NH) {
        float acc = bg2[ln];
#pragma unroll 4
        for (int k = 0; k < WH; k++) acc += ys[w][k] * W2s[k * NH + ln];
        gates[(size_t)tok * NH + ln] = 1.f / (1.f + __expf(-acc));
    }
}

// ============ mask precompute ============
__global__ __launch_bounds__(512) void mask_prep(const float* __restrict__ am,
                                                 float* __restrict__ msk)
{
    int i = blockIdx.x * 512 + threadIdx.x;
    msk[i] = (1.f - am[i]) * -10000.f;
}

// ============ attention: SW-pipelined, packed Ps, interleaved-K, fp16 e out (R13, 653us) ============
#define KSTR 72
#define VSTR 72
#define PSZ  5120

__global__ __launch_bounds__(512) void attn_onepass(float* __restrict__ rowinv)
{
    extern __shared__ float sm[];
    float* Qs    = sm;                    // 64x68
    float* KsA   = Qs + 4352;             // 3 x 64x72
    float* VsA   = KsA + 3 * 64 * KSTR;   // 3 x 64x72
    float* PsA   = VsA + 3 * 64 * VSTR;   // 2 x PSZ packed
    float* gt    = PsA + 2 * PSZ;
    float* redS  = gt + 64;
    float* rowIs = redS + 256;

    const int t = threadIdx.x, lane = t & 31, w = t >> 5;
    const int wr = w >> 2, wk = w & 3;
    const int qr = lane >> 2, qc = lane & 3;
    const int q0 = blockIdx.x * 64;
    const int h  = blockIdx.y;
    const int b  = blockIdx.z;
    const int NT = S / 64;

    const float* Qg = g_Q + ((size_t)(b * S + q0)) * H + h * DH;
    const float* Kg = g_K + ((size_t)b * S) * H + h * DH;
    const float* Vg = g_V + ((size_t)b * S) * H + h * DH;
    const float* mskb = g_msk + (size_t)b * S;
    __half* eout = g_eh + (((size_t)b * NH + h) * S + q0) * S;

    auto issueKV = [&](int kt){
        int buf = kt % 3;
        float* Kd = KsA + buf * 64 * KSTR;
        float* Vd = VsA + buf * 64 * VSTR;
#pragma unroll
        for (int i = 0; i < 2; i++) {
            int idx = t + i * 512;
            int r = idx >> 4, c4 = (idx & 15) * 4;
            cpa16(&Kd[r * KSTR + c4], &Kg[(size_t)(kt * 64 + r) * H + c4]);
            cpa16(&Vd[r * VSTR + c4], &Vg[(size_t)(kt * 64 + r) * H + c4]);
        }
    };

    {
#pragma unroll
        for (int i = 0; i < 2; i++) {
            int idx = t + i * 512;
            int r = idx >> 4, c4 = (idx & 15) * 4;
            cpa16(&Qs[r * 68 + c4], &Qg[(size_t)r * H + c4]);
        }
        issueKV(0);
        CPA_COMMIT();
        if (t < 64) gt[t] = g_gates[(size_t)(b * S + q0 + t) * NH + h] * 0.125f;
        CPA_WAIT0();
    }
    __syncthreads();

    const float g0 = gt[wr * 16 + qr], g1v = gt[wr * 16 + qr + 8];
    const int r0 = (wr * 16 + qr) * 68, r1 = (wr * 16 + qr + 8) * 68;

    uint32_t qa[8][4];
#pragma unroll
    for (int ks = 0; ks < 8; ks++) {
        int kc = ks * 8 + qc;
        qa[ks][0] = F2U(Qs[r0 + kc]);
        qa[ks][1] = F2U(Qs[r1 + kc]);
        qa[ks][2] = F2U(Qs[r0 + kc + 4]);
        qa[ks][3] = F2U(Qs[r1 + kc + 4]);
    }

    float s0 = 0.f, s1 = 0.f;
    float cacc[2][4] = {{0.f,0.f,0.f,0.f},{0.f,0.f,0.f,0.f}};

    const int qcA   = (qc < 2) ? 2 * qc : 2 * qc - 4;
    const int slotA = (qc < 2) ? 0 : 2;

    auto doPV = [&](int j){
        const float* Pb = PsA + (j & 1) * PSZ;
        const float* Vb = VsA + (j % 3) * 64 * VSTR;
#pragma unroll
        for (int ks = 0; ks < 8; ks++) {
            float4 av = *(const float4*)&Pb[((wr * 8 + ks) * 4 + qc) * 40 + qr * 4];
#pragma unroll
            for (int j2 = 0; j2 < 2; j2++) {
                int nb = (wk * 2 + j2) * 8;
                uint32_t bb[2];
                bb[0] = F2U(Vb[(ks * 8 + qc) * VSTR + nb + qr]);
                bb[1] = F2U(Vb[(ks * 8 + qc + 4) * VSTR + nb + qr]);
                mma8(cacc[j2], (const uint32_t*)&av, bb);
            }
        }
    };

    for (int kt = 0; kt < NT; kt++) {
        if (kt > 0) { CPA_WAIT0(); __syncthreads(); }
        if (kt + 1 < NT) { issueKV(kt + 1); CPA_COMMIT(); }

        {
            const float* Kb = KsA + (kt % 3) * 64 * KSTR;
            float* Pw = PsA + (kt & 1) * PSZ;
            float c0[4] = {0.f,0.f,0.f,0.f}, c1[4] = {0.f,0.f,0.f,0.f};
#pragma unroll
            for (int ks = 0; ks < 8; ks++) {
                float2 bv0 = *(const float2*)&Kb[(wk * 16 + qr) * KSTR + ks * 8 + 2 * qc];
                mma8(c0, qa[ks], (const uint32_t*)&bv0);
                float2 bv1 = *(const float2*)&Kb[(wk * 16 + 8 + qr) * KSTR + ks * 8 + 2 * qc];
                mma8(c1, qa[ks], (const uint32_t*)&bv1);
            }
#pragma unroll
            for (int nt = 0; nt < 2; nt++) {
                float* c = nt ? c1 : c0;
                int lc = wk * 16 + nt * 8 + 2 * qc;
                int col = kt * 64 + lc;
                float2 mk = __ldg((const float2*)&mskb[col]);
                float e00 = __expf(c[0] * g0  + mk.x);
                float e01 = __expf(c[1] * g0  + mk.y);
                float e10 = __expf(c[2] * g1v + mk.x);
                float e11 = __expf(c[3] * g1v + mk.y);
                s0 += e00 + e01;
                s1 += e10 + e11;
                int ksl = wk * 2 + nt;
                float* basep = Pw + ((wr * 8 + ksl) * 4 + qcA) * 40 + qr * 4 + slotA;
                *(float2*)basep        = make_float2(e00, e10);
                *(float2*)(basep + 40) = make_float2(e01, e11);
                *(__half2*)&eout[(size_t)(wr * 16 + qr) * S + col]     = __floats2half2_rn(e00, e01);
                *(__half2*)&eout[(size_t)(wr * 16 + qr + 8) * S + col] = __floats2half2_rn(e10, e11);
            }
        }

        if (kt > 0) doPV(kt - 1);
    }
    __syncthreads();
    doPV(NT - 1);

#pragma unroll
    for (int off = 1; off <= 2; off <<= 1) {
        s0 += __shfl_xor_sync(0xffffffffu, s0, off);
        s1 += __shfl_xor_sync(0xffffffffu, s1, off);
    }
    if (qc == 0) {
        redS[wk * 64 + wr * 16 + qr]     = s0;
        redS[wk * 64 + wr * 16 + qr + 8] = s1;
    }
    __syncthreads();
    if (t < 64) {
        float s = redS[t] + redS[64 + t] + redS[128 + t] + redS[192 + t];
        float inv = 1.f / s;
        rowIs[t] = inv;
        rowinv[((size_t)b * NH + h) * S + q0 + t] = inv;
    }
    __syncthreads();
    const float I0 = rowIs[wr * 16 + qr], I1 = rowIs[wr * 16 + qr + 8];

#pragma unroll
    for (int j = 0; j < 2; j++) {
        int nb = (wk * 2 + j) * 8;
        size_t row = (size_t)b * S + q0 + wr * 16 + qr;
        int col = h * DH + nb + 2 * qc;
        *(float2*)&g_ctx[row * H + col]       = make_float2(cacc[j][0] * I0, cacc[j][1] * I0);
        *(float2*)&g_ctx[(row + 8) * H + col] = make_float2(cacc[j][2] * I1, cacc[j][3] * I1);
    }
}

// ============ probs normalization: fp16 e -> fp32, fully coalesced ============
// thread t: 8B uint2 load (4 halves) at t*8B; 16B float4 store at t*16B. 512 thr = 1 row.
__global__ __launch_bounds__(512) void scale_probs(float* __restrict__ probs,
                                                   const float* __restrict__ rowinv)
{
    const size_t row = blockIdx.x;
    const float inv = __ldg(&rowinv[row]);
    const int t = threadIdx.x;
    const __half2* er = (const __half2*)(g_eh + row * (size_t)S);
    __half2 h0 = er[t * 2];
    __half2 h1 = er[t * 2 + 1];
    float2 f0 = __half22float2(h0);
    float2 f1 = __half22float2(h1);
    float4 o = make_float4(f0.x * inv, f0.y * inv, f1.x * inv, f1.y * inv);
    ((float4*)(probs + row * (size_t)S))[t] = o;
}

// ============ residual + LayerNorm(768) ============
__global__ __launch_bounds__(256) void ln_kernel(const float* __restrict__ P,
                                                 const float* __restrict__ Xres,
                                                 const float* __restrict__ wgt,
                                                 const float* __restrict__ bb,
                                                 float* __restrict__ out)
{
    const int tok = blockIdx.x;
    const int t = threadIdx.x;
    __shared__ float rs[8], rq[8];
    __shared__ float smu, siv;

    float v[3];
    float s = 0.f, sq = 0.f;
#pragma unroll
    for (int i = 0; i < 3; i++) {
        int c = t + i * 256;
        float x = P[(size_t)tok * H + c] + Xres[(size_t)tok * H + c];
        v[i] = x; s += x; sq += x * x;
    }
    for (int o = 16; o; o >>= 1) {
        s  += __shfl_xor_sync(0xffffffffu, s, o);
        sq += __shfl_xor_sync(0xffffffffu, sq, o);
    }
    int wi = t >> 5, ln = t & 31;
    if (ln == 0) { rs[wi] = s; rq[wi] = sq; }
    __syncthreads();
    if (t == 0) {
        float ts = 0.f, tq = 0.f;
#pragma unroll
        for (int i = 0; i < 8; i++) { ts += rs[i]; tq += rq[i]; }
        float mu = ts * (1.f / H);
        smu = mu;
        siv = rsqrtf(tq * (1.f / H) - mu * mu + EPS);
    }
    __syncthreads();
    float mu = smu, iv = siv;
#pragma unroll
    for (int i = 0; i < 3; i++) {
        int c = t + i * 256;
        out[(size_t)tok * H + c] = (v[i] - mu) * iv * wgt[c] + bb[c];
    }
}

// ============ launch ============
extern "C" void kernel_launch(void* const* d_in, const int* in_sizes, int n_in,
                              void* d_out, int out_size)
{
    const float* X    = (const float*)d_in[0];
    const float* am   = (const float*)d_in[1];
    const float* Wq   = (const float*)d_in[2];
    const float* bq   = (const float*)d_in[3];
    const float* Wk   = (const float*)d_in[4];
    const float* bk   = (const float*)d_in[5];
    const float* Wv   = (const float*)d_in[6];
    const float* bv   = (const float*)d_in[7];
    const float* Wg1  = (const float*)d_in[8];
    const float* bg1  = (const float*)d_in[9];
    const float* glnw = (const float*)d_in[10];
    const float* glnb = (const float*)d_in[11];
    const float* Wg2  = (const float*)d_in[12];
    const float* bg2  = (const float*)d_in[13];
    const float* Wo   = (const float*)d_in[14];
    const float* bo   = (const float*)d_in[15];
    const float* lnw  = (const float*)d_in[16];
    const float* lnb  = (const float*)d_in[17];

    float* out   = (float*)d_out;
    float* probs = out + (size_t)B * S * H;

    float *Qp, *Kp, *Vp, *Cp, *Pp, *G1p, *Gp, *Rp, *Mp;
    cudaGetSymbolAddress((void**)&Qp, g_Q);
    cudaGetSymbolAddress((void**)&Kp, g_K);
    cudaGetSymbolAddress((void**)&Vp, g_V);
    cudaGetSymbolAddress((void**)&Cp, g_ctx);
    cudaGetSymbolAddress((void**)&Pp, g_proj);
    cudaGetSymbolAddress((void**)&G1p, g_g1);
    cudaGetSymbolAddress((void**)&Gp, g_gates);
    cudaGetSymbolAddress((void**)&Rp, g_rowinv);
    cudaGetSymbolAddress((void**)&Mp, g_msk);

    dim3 gfused(19, TOK / GBM);
    gemm_qkvg<<<gfused, 256>>>(X, Wq, bq, Wk, bk, Wv, bv, Wg1, bg1, Qp, Kp, Vp, G1p);

    gate2_kernel<<<TOK / 8, 256>>>(G1p, glnw, glnb, Wg2, bg2, Gp);

    mask_prep<<<B * S / 512, 512>>>(am, Mp);

    size_t att_smem = (size_t)(4352 + 3*64*KSTR + 3*64*VSTR + 2*PSZ + 64 + 256 + 64) * sizeof(float);
    cudaFuncSetAttribute(attn_onepass, cudaFuncAttributeMaxDynamicSharedMemorySize, (int)att_smem);
    dim3 gatt(S / 64, NH, B);
    attn_onepass<<<gatt, 512, att_smem>>>(Rp);

    scale_probs<<<B * NH * S, 512>>>(probs, Rp);

    dim3 ggemm(H / GBN, TOK / GBM);
    gemm_tf32<<<ggemm, 256>>>(Cp, Wo, bo, Pp, TOK, H, H);

    ln_kernel<<<TOK, 256>>>(Pp, X, lnw, lnb, out);
}